// round 16
// baseline (speedup 1.0000x reference)
#include <cuda_runtime.h>
#include <cuda_fp16.h>
#include <cstdint>

// AdaMoeLayer: out[t] = sum_e w[t,e]*(x[t] @ W_e + b_e),  T=32768, D=512, E=8.
// R16: sparse grouped GEMM, single fp16 product. Warp tile 32x64 (4m x 2n
// layout) so each B fragment feeds 2 MMAs: LDS/MMA cut 33% vs R15.
// 3-stage cp.async ring, pad masking, bias fused in gating, red.v2 epilogue.

#define D_DIM 512
#define E_DIM 8
#define T_TOK 32768
#define MAX_THRESHOLD 0.25f

// ---- static device scratch ----
__device__ float g_w[T_TOK * E_DIM];                       // gate weights, 1 MB
__device__ int   g_cnt[E_DIM];                             // per-expert counts
__device__ int   g_list[(size_t)E_DIM * T_TOK];            // token ids, 1 MB
__device__ float g_wval[(size_t)E_DIM * T_TOK];            // weights,   1 MB
__device__ __half g_Wh[(size_t)E_DIM * D_DIM * D_DIM];     // fp16 W' [e][n][k-perm]
__device__ __half g_Xh[(size_t)T_TOK * D_DIM];             // fp16 X [t][k-perm]

// ---------------------------------------------------------------------------
__device__ __forceinline__ uint32_t smem_u32(const void* p) {
    uint32_t a;
    asm("{ .reg .u64 t; cvta.to.shared.u64 t, %1; cvt.u32.u64 %0, t; }"
        : "=r"(a) : "l"(p));
    return a;
}
__device__ __forceinline__ void cp16(uint32_t dst, const void* src) {
    asm volatile("cp.async.cg.shared.global [%0], [%1], 16;\n"
                 :: "r"(dst), "l"(__cvta_generic_to_global(src)) : "memory");
}
__device__ __forceinline__ void mma_f16(float* c,
    uint32_t a0, uint32_t a1, uint32_t a2, uint32_t a3,
    uint32_t b0, uint32_t b1)
{
    asm volatile(
        "mma.sync.aligned.m16n8k16.row.col.f32.f16.f16.f32 "
        "{%0,%1,%2,%3}, {%4,%5,%6,%7}, {%8,%9}, {%0,%1,%2,%3};"
        : "+f"(c[0]), "+f"(c[1]), "+f"(c[2]), "+f"(c[3])
        : "r"(a0), "r"(a1), "r"(a2), "r"(a3), "r"(b0), "r"(b1));
}
__device__ __forceinline__ void red_add_v2(float* addr, float v0, float v1) {
    asm volatile("red.global.add.v2.f32 [%0], {%1, %2};"
                 :: "l"(addr), "f"(v0), "f"(v1) : "memory");
}

// ---------------------------------------------------------------------------
// Kernel 1: W[e][k][n] -> fp16 W'[e][n][k-perm]. Also zeroes g_cnt.
// ---------------------------------------------------------------------------
__global__ void wprep_kernel(const float* __restrict__ W)
{
    __shared__ float tile[32][33];
    int e = blockIdx.z;
    int nb = blockIdx.x * 32, kb = blockIdx.y * 32;
    int tx = threadIdx.x, ty = threadIdx.y;   // 32 x 8
    if (blockIdx.x == 0 && blockIdx.y == 0 && blockIdx.z == 0 &&
        ty == 0 && tx < E_DIM)
        g_cnt[tx] = 0;
    const float* Ws = W + (size_t)e * D_DIM * D_DIM;
#pragma unroll
    for (int j = 0; j < 32; j += 8)
        tile[ty + j][tx] = Ws[(size_t)(kb + ty + j) * D_DIM + nb + tx];
    __syncthreads();
    int grp = tx >> 4, p = (tx & 15) >> 1, lo = tx & 1;
    int s = (p < 4) ? 2 * p : 2 * (p - 4) + 1;
    int kp = kb + grp * 16 + s * 2 + lo;
#pragma unroll
    for (int j = 0; j < 32; j += 8)
        g_Wh[((size_t)e * D_DIM + nb + ty + j) * D_DIM + kp] =
            __float2half(tile[tx][ty + j]);
}

// ---------------------------------------------------------------------------
// Kernel 2: gating + list append + fused X->fp16 (pair-permuted) + fused
// bias write. One warp per token.
// ---------------------------------------------------------------------------
__global__ __launch_bounds__(256) void gating_kernel(
    const float* __restrict__ x,
    const float* __restrict__ Wg, const float* __restrict__ bg,
    const float* __restrict__ Wt, const float* __restrict__ bt,
    const float* __restrict__ bexp, float* __restrict__ out)
{
    __shared__ float sWg[E_DIM][D_DIM];
    __shared__ float sWt[D_DIM];
    __shared__ float sB[E_DIM][D_DIM];
    const int tid = threadIdx.x;
    for (int i = tid; i < E_DIM * D_DIM; i += 256) {
        int e = i / D_DIM, d = i - e * D_DIM;
        sWg[e][d] = Wg[d * E_DIM + e];
        sB[e][d] = bexp[i];
    }
    for (int i = tid; i < D_DIM; i += 256) sWt[i] = Wt[i];
    __syncthreads();

    const int warp = tid >> 5, lane = tid & 31;
    const int t = blockIdx.x * 8 + warp;
    const float* xr = x + (size_t)t * D_DIM;
    uint32_t* xh_u = reinterpret_cast<uint32_t*>(g_Xh) + (size_t)t * 256;

    float acc[9];
#pragma unroll
    for (int e = 0; e < 9; e++) acc[e] = 0.f;
#pragma unroll
    for (int i = 0; i < 8; i++) {
        int d = 2 * lane + 64 * i;
        float2 xv = *reinterpret_cast<const float2*>(xr + d);
#pragma unroll
        for (int e = 0; e < E_DIM; e++)
            acc[e] = fmaf(xv.y, sWg[e][d + 1], fmaf(xv.x, sWg[e][d], acc[e]));
        acc[8] = fmaf(xv.y, sWt[d + 1], fmaf(xv.x, sWt[d], acc[8]));

        __half2 ph = __float22half2_rn(xv);
        int pg = lane + 32 * i;               // global pair index
        int g16 = pg >> 3, p = pg & 7;
        int s = (p < 4) ? 2 * p : 2 * (p - 4) + 1;
        xh_u[g16 * 8 + s] = *reinterpret_cast<uint32_t*>(&ph);
    }
#pragma unroll
    for (int off = 16; off > 0; off >>= 1)
#pragma unroll
        for (int e = 0; e < 9; e++) acc[e] += __shfl_xor_sync(0xffffffffu, acc[e], off);

    float logit[E_DIM];
#pragma unroll
    for (int e = 0; e < E_DIM; e++) logit[e] = acc[e] + bg[e];
    float m = logit[0];
#pragma unroll
    for (int e = 1; e < E_DIM; e++) m = fmaxf(m, logit[e]);
    float p[E_DIM], s = 0.f;
#pragma unroll
    for (int e = 0; e < E_DIM; e++) { p[e] = expf(logit[e] - m); s += p[e]; }
    float inv_s = 1.f / s;
    float thr = (1.f / (1.f + expf(-(acc[8] + bt[0])))) * MAX_THRESHOLD;

    float w[E_DIM], ws = 0.f;
#pragma unroll
    for (int e = 0; e < E_DIM; e++) {
        float a = p[e] * inv_s - thr;
        w[e] = (a >= 0.f) ? a : 0.f;
        ws += w[e];
    }
    if (ws == 0.f) ws = 1.f;
    float inv_ws = 1.f / ws;
    float wn[E_DIM];
#pragma unroll
    for (int e = 0; e < E_DIM; e++) wn[e] = w[e] * inv_ws;

    if (lane < E_DIM) {
        float v = 0.f;
#pragma unroll
        for (int e = 0; e < E_DIM; e++) if (lane == e) v = wn[e];
        g_w[t * E_DIM + lane] = v;
        if (v > 0.f) {
            int pos = atomicAdd(&g_cnt[lane], 1);
            g_list[(size_t)lane * T_TOK + pos] = t;
            g_wval[(size_t)lane * T_TOK + pos] = v;
        }
    }

    // fused bias: out[t][n] = sum_e wn[e]*b_e[n]
#pragma unroll
    for (int i = 0; i < 4; i++) {
        int c = lane * 4 + i * 128;
        float4 a4 = make_float4(0.f, 0.f, 0.f, 0.f);
#pragma unroll
        for (int e = 0; e < E_DIM; e++) {
            float4 b4 = *reinterpret_cast<const float4*>(&sB[e][c]);
            a4.x = fmaf(wn[e], b4.x, a4.x);
            a4.y = fmaf(wn[e], b4.y, a4.y);
            a4.z = fmaf(wn[e], b4.z, a4.z);
            a4.w = fmaf(wn[e], b4.w, a4.w);
        }
        *reinterpret_cast<float4*>(out + (size_t)t * D_DIM + c) = a4;
    }
}

// ---------------------------------------------------------------------------
// Kernel 3: sparse grouped GEMM. Grid (4 N-tiles, 256 M-tiles, 8 experts),
// 256 thr, 2 CTAs/SM. CTA: 128 gathered tokens x 128 cols; warps 4m x 2n,
// warp tile 32x64 (B fragments amortized over 2 m16 tiles). K=512 in 8 k64
// chunks, 3-stage cp.async ring, one sync/stage. Epilogue: red.v2 scatter.
// ---------------------------------------------------------------------------
#define XBUF 4096                             // u32: 128 rows x 32
#define BBUF 4096                             // u32: 128 rows x 32
#define IDX_OFF 0                             // 128 ints
#define WV_OFF 128                            // 128 floats
#define X_OFF 256                             // 3 buffers
#define B_OFF (X_OFF + 3 * XBUF)              // 12544; 3 buffers
#define SMEM_U32 (B_OFF + 3 * BBUF)           // 24832
#define SMEM_BYTES (SMEM_U32 * 4)             // 99328

__device__ __forceinline__ void issue_stage(
    int tid, uint32_t sm_base, const int* sIdx, int e, int kt, int n0)
{
    const int buf = kt % 3;
#pragma unroll
    for (int i = 0; i < 4; i++) {
        int id = tid + (i << 8);
        int row = id >> 3, ch = id & 7;
        uint32_t wo = (uint32_t)((ch * 4) ^ ((row & 3) * 8));
        cp16(sm_base + (X_OFF + buf * XBUF + row * 32 + wo) * 4,
             g_Xh + (size_t)sIdx[row] * D_DIM + kt * 64 + ch * 8);
        cp16(sm_base + (B_OFF + buf * BBUF + row * 32 + wo) * 4,
             g_Wh + ((size_t)e * D_DIM + n0 + row) * D_DIM + kt * 64 + ch * 8);
    }
    asm volatile("cp.async.commit_group;\n" ::: "memory");
}

__global__ __launch_bounds__(256, 2) void moe_mma_kernel(float* __restrict__ out)
{
    const int e = blockIdx.z;
    const int m0 = blockIdx.y * 128;
    const int cnt = g_cnt[e];
    if (m0 >= cnt) return;

    extern __shared__ float smem[];
    uint32_t* smemU = reinterpret_cast<uint32_t*>(smem);
    int* sIdx = reinterpret_cast<int*>(smem + IDX_OFF);
    float* sW = smem + WV_OFF;
    const uint32_t sm_base = smem_u32(smem);
    const int tid = threadIdx.x;
    const int lane = tid & 31, wid = tid >> 5;
    const int g = lane >> 2, t4 = lane & 3;
    const int wm = (wid >> 1) * 32, wn = (wid & 1) * 64;
    const int n0 = blockIdx.x * 128;
    const int r0 = wm + g;
    const int swz = (g & 3) * 8;

    if (tid < 128) {
        int idx = m0 + tid;
        if (idx < cnt) {
            sIdx[tid] = g_list[(size_t)e * T_TOK + idx];
            sW[tid]   = g_wval[(size_t)e * T_TOK + idx];
        } else {
            sIdx[tid] = 0;
            sW[tid]   = 0.f;
        }
    }
    __syncthreads();

    float acc[2][8][4];
#pragma unroll
    for (int mt = 0; mt < 2; mt++)
#pragma unroll
        for (int nt = 0; nt < 8; nt++)
#pragma unroll
            for (int j = 0; j < 4; j++) acc[mt][nt][j] = 0.f;

    issue_stage(tid, sm_base, sIdx, e, 0, n0);
    issue_stage(tid, sm_base, sIdx, e, 1, n0);

#pragma unroll 1
    for (int kt = 0; kt < 8; ++kt) {
        if (kt + 1 < 8) asm volatile("cp.async.wait_group 1;\n" ::: "memory");
        else            asm volatile("cp.async.wait_group 0;\n" ::: "memory");
        __syncthreads();                       // stage kt ready; buf (kt+2)%3 free
        if (kt + 2 < 8) issue_stage(tid, sm_base, sIdx, e, kt + 2, n0);

        const uint32_t* Xb = smemU + X_OFF + (kt % 3) * XBUF;
        const uint32_t* Bb = smemU + B_OFF + (kt % 3) * BBUF;

#pragma unroll
        for (int j = 0; j < 4; j++) {
            uint32_t wo = (uint32_t)((j * 8 + t4 * 2) ^ swz);
            uint2 a00 = *reinterpret_cast<const uint2*>(Xb + r0 * 32 + wo);
            uint2 a01 = *reinterpret_cast<const uint2*>(Xb + (r0 + 8) * 32 + wo);
            uint2 a10 = *reinterpret_cast<const uint2*>(Xb + (r0 + 16) * 32 + wo);
            uint2 a11 = *reinterpret_cast<const uint2*>(Xb + (r0 + 24) * 32 + wo);
#pragma unroll
            for (int nt = 0; nt < 8; nt++) {
                uint2 b = *reinterpret_cast<const uint2*>(
                    Bb + (wn + nt * 8 + g) * 32 + wo);
                mma_f16(acc[0][nt], a00.x, a01.x, a00.y, a01.y, b.x, b.y);
                mma_f16(acc[1][nt], a10.x, a11.x, a10.y, a11.y, b.x, b.y);
            }
        }
    }

    // ---- epilogue: out[t][n] += w * acc (vector red; pads have w==0) ----
#pragma unroll
    for (int mt = 0; mt < 2; mt++) {
#pragma unroll
        for (int rr = 0; rr < 2; rr++) {
            int row_l = r0 + mt * 16 + rr * 8;
            float wv = sW[row_l];
            if (wv > 0.f) {
                float* base = out + (size_t)sIdx[row_l] * D_DIM + n0 + wn;
#pragma unroll
                for (int nt = 0; nt < 8; nt++) {
                    int cl = nt * 8 + 2 * t4;
                    red_add_v2(base + cl, wv * acc[mt][nt][rr * 2 + 0],
                                          wv * acc[mt][nt][rr * 2 + 1]);
                }
            }
        }
    }
}

// ---------------------------------------------------------------------------
extern "C" void kernel_launch(void* const* d_in, const int* in_sizes, int n_in,
                              void* d_out, int out_size)
{
    const float* x    = (const float*)d_in[0];
    const float* Wg   = (const float*)d_in[1];
    const float* bg   = (const float*)d_in[2];
    const float* Wt   = (const float*)d_in[3];
    const float* bt   = (const float*)d_in[4];
    const float* Wexp = (const float*)d_in[5];
    const float* bexp = (const float*)d_in[6];
    float* out        = (float*)d_out;

    const int T = in_sizes[0] / D_DIM;          // 32768

    cudaFuncSetAttribute(moe_mma_kernel,
                         cudaFuncAttributeMaxDynamicSharedMemorySize, SMEM_BYTES);

    wprep_kernel<<<dim3(16, 16, 8), dim3(32, 8)>>>(Wexp);   // also zeroes g_cnt
    gating_kernel<<<T / 8, 256>>>(x, Wg, bg, Wt, bt, bexp, out);
    moe_mma_kernel<<<dim3(4, T / 128, E_DIM), 256, SMEM_BYTES>>>(out);
}

// round 17
// speedup vs baseline: 1.0601x; 1.0601x over previous
#include <cuda_runtime.h>
#include <cuda_fp16.h>
#include <cstdint>

// AdaMoeLayer: out[t] = sum_e w[t,e]*(x[t] @ W_e + b_e),  T=32768, D=512, E=8.
// R17: sparse grouped GEMM, single fp16 product, ldmatrix.x4 fragment loads
// (72 LDS.64 -> 36 LDSM.x4 per stage/warp), plain [row][k] layouts (no pair
// permutation), chunk^row&7 swizzle. 3-stage cp.async ring, bias fused in
// gating, red.global.add.v2.f32 scatter epilogue.

#define D_DIM 512
#define E_DIM 8
#define T_TOK 32768
#define MAX_THRESHOLD 0.25f

// ---- static device scratch ----
__device__ float g_w[T_TOK * E_DIM];                       // gate weights, 1 MB
__device__ int   g_cnt[E_DIM];                             // per-expert counts
__device__ int   g_list[(size_t)E_DIM * T_TOK];            // token ids, 1 MB
__device__ float g_wval[(size_t)E_DIM * T_TOK];            // weights,   1 MB
__device__ __half g_Wh[(size_t)E_DIM * D_DIM * D_DIM];     // fp16 W' [e][n][k]
__device__ __half g_Xh[(size_t)T_TOK * D_DIM];             // fp16 X [t][k]

// ---------------------------------------------------------------------------
__device__ __forceinline__ uint32_t smem_u32(const void* p) {
    uint32_t a;
    asm("{ .reg .u64 t; cvta.to.shared.u64 t, %1; cvt.u32.u64 %0, t; }"
        : "=r"(a) : "l"(p));
    return a;
}
__device__ __forceinline__ void cp16(uint32_t dst, const void* src) {
    asm volatile("cp.async.cg.shared.global [%0], [%1], 16;\n"
                 :: "r"(dst), "l"(__cvta_generic_to_global(src)) : "memory");
}
__device__ __forceinline__ void mma_f16(float* c,
    uint32_t a0, uint32_t a1, uint32_t a2, uint32_t a3,
    uint32_t b0, uint32_t b1)
{
    asm volatile(
        "mma.sync.aligned.m16n8k16.row.col.f32.f16.f16.f32 "
        "{%0,%1,%2,%3}, {%4,%5,%6,%7}, {%8,%9}, {%0,%1,%2,%3};"
        : "+f"(c[0]), "+f"(c[1]), "+f"(c[2]), "+f"(c[3])
        : "r"(a0), "r"(a1), "r"(a2), "r"(a3), "r"(b0), "r"(b1));
}
__device__ __forceinline__ void ldsm_x4(
    uint32_t& r0, uint32_t& r1, uint32_t& r2, uint32_t& r3, uint32_t addr)
{
    asm volatile("ldmatrix.sync.aligned.m8n8.x4.shared.b16 {%0,%1,%2,%3}, [%4];"
        : "=r"(r0), "=r"(r1), "=r"(r2), "=r"(r3) : "r"(addr));
}
__device__ __forceinline__ void red_add_v2(float* addr, float v0, float v1) {
    asm volatile("red.global.add.v2.f32 [%0], {%1, %2};"
                 :: "l"(addr), "f"(v0), "f"(v1) : "memory");
}

// ---------------------------------------------------------------------------
// Kernel 1: W[e][k][n] -> fp16 W'[e][n][k] (plain). Also zeroes g_cnt.
// ---------------------------------------------------------------------------
__global__ void wprep_kernel(const float* __restrict__ W)
{
    __shared__ float tile[32][33];
    int e = blockIdx.z;
    int nb = blockIdx.x * 32, kb = blockIdx.y * 32;
    int tx = threadIdx.x, ty = threadIdx.y;   // 32 x 8
    if (blockIdx.x == 0 && blockIdx.y == 0 && blockIdx.z == 0 &&
        ty == 0 && tx < E_DIM)
        g_cnt[tx] = 0;
    const float* Ws = W + (size_t)e * D_DIM * D_DIM;
#pragma unroll
    for (int j = 0; j < 32; j += 8)
        tile[ty + j][tx] = Ws[(size_t)(kb + ty + j) * D_DIM + nb + tx];
    __syncthreads();
#pragma unroll
    for (int j = 0; j < 32; j += 8)
        g_Wh[((size_t)e * D_DIM + nb + ty + j) * D_DIM + kb + tx] =
            __float2half(tile[tx][ty + j]);
}

// ---------------------------------------------------------------------------
// Kernel 2: gating + list append + fused X->fp16 (plain) + fused bias write.
// One warp per token.
// ---------------------------------------------------------------------------
__global__ __launch_bounds__(256) void gating_kernel(
    const float* __restrict__ x,
    const float* __restrict__ Wg, const float* __restrict__ bg,
    const float* __restrict__ Wt, const float* __restrict__ bt,
    const float* __restrict__ bexp, float* __restrict__ out)
{
    __shared__ float sWg[E_DIM][D_DIM];
    __shared__ float sWt[D_DIM];
    __shared__ float sB[E_DIM][D_DIM];
    const int tid = threadIdx.x;
    for (int i = tid; i < E_DIM * D_DIM; i += 256) {
        int e = i / D_DIM, d = i - e * D_DIM;
        sWg[e][d] = Wg[d * E_DIM + e];
        sB[e][d] = bexp[i];
    }
    for (int i = tid; i < D_DIM; i += 256) sWt[i] = Wt[i];
    __syncthreads();

    const int warp = tid >> 5, lane = tid & 31;
    const int t = blockIdx.x * 8 + warp;
    const float* xr = x + (size_t)t * D_DIM;
    uint32_t* xh_u = reinterpret_cast<uint32_t*>(g_Xh) + (size_t)t * 256;

    float acc[9];
#pragma unroll
    for (int e = 0; e < 9; e++) acc[e] = 0.f;
#pragma unroll
    for (int i = 0; i < 8; i++) {
        int d = 2 * lane + 64 * i;
        float2 xv = *reinterpret_cast<const float2*>(xr + d);
#pragma unroll
        for (int e = 0; e < E_DIM; e++)
            acc[e] = fmaf(xv.y, sWg[e][d + 1], fmaf(xv.x, sWg[e][d], acc[e]));
        acc[8] = fmaf(xv.y, sWt[d + 1], fmaf(xv.x, sWt[d], acc[8]));

        __half2 ph = __float22half2_rn(xv);
        xh_u[lane + 32 * i] = *reinterpret_cast<uint32_t*>(&ph);
    }
#pragma unroll
    for (int off = 16; off > 0; off >>= 1)
#pragma unroll
        for (int e = 0; e < 9; e++) acc[e] += __shfl_xor_sync(0xffffffffu, acc[e], off);

    float logit[E_DIM];
#pragma unroll
    for (int e = 0; e < E_DIM; e++) logit[e] = acc[e] + bg[e];
    float m = logit[0];
#pragma unroll
    for (int e = 1; e < E_DIM; e++) m = fmaxf(m, logit[e]);
    float p[E_DIM], s = 0.f;
#pragma unroll
    for (int e = 0; e < E_DIM; e++) { p[e] = expf(logit[e] - m); s += p[e]; }
    float inv_s = 1.f / s;
    float thr = (1.f / (1.f + expf(-(acc[8] + bt[0])))) * MAX_THRESHOLD;

    float w[E_DIM], ws = 0.f;
#pragma unroll
    for (int e = 0; e < E_DIM; e++) {
        float a = p[e] * inv_s - thr;
        w[e] = (a >= 0.f) ? a : 0.f;
        ws += w[e];
    }
    if (ws == 0.f) ws = 1.f;
    float inv_ws = 1.f / ws;
    float wn[E_DIM];
#pragma unroll
    for (int e = 0; e < E_DIM; e++) wn[e] = w[e] * inv_ws;

    if (lane < E_DIM) {
        float v = 0.f;
#pragma unroll
        for (int e = 0; e < E_DIM; e++) if (lane == e) v = wn[e];
        g_w[t * E_DIM + lane] = v;
        if (v > 0.f) {
            int pos = atomicAdd(&g_cnt[lane], 1);
            g_list[(size_t)lane * T_TOK + pos] = t;
            g_wval[(size_t)lane * T_TOK + pos] = v;
        }
    }

    // fused bias: out[t][n] = sum_e wn[e]*b_e[n]
#pragma unroll
    for (int i = 0; i < 4; i++) {
        int c = lane * 4 + i * 128;
        float4 a4 = make_float4(0.f, 0.f, 0.f, 0.f);
#pragma unroll
        for (int e = 0; e < E_DIM; e++) {
            float4 b4 = *reinterpret_cast<const float4*>(&sB[e][c]);
            a4.x = fmaf(wn[e], b4.x, a4.x);
            a4.y = fmaf(wn[e], b4.y, a4.y);
            a4.z = fmaf(wn[e], b4.z, a4.z);
            a4.w = fmaf(wn[e], b4.w, a4.w);
        }
        *reinterpret_cast<float4*>(out + (size_t)t * D_DIM + c) = a4;
    }
}

// ---------------------------------------------------------------------------
// Kernel 3: sparse grouped GEMM. Grid (4 N-tiles, 256 M-tiles, 8 experts),
// 256 thr, 2 CTAs/SM. CTA: 128 gathered tokens x 128 cols; warp = 16x128.
// Fragments via ldmatrix.x4; swizzle chunk ^ (row&7). 8 k64 chunks, 3-stage
// cp.async ring, one sync/stage. Epilogue: red.v2 w*acc into out.
// ---------------------------------------------------------------------------
#define XBUF 4096                             // u32: 128 rows x 32
#define BBUF 4096                             // u32: 128 rows x 32
#define IDX_OFF 0                             // 128 ints
#define WV_OFF 128                            // 128 floats
#define X_OFF 256                             // 3 buffers
#define B_OFF (X_OFF + 3 * XBUF)              // 12544; 3 buffers
#define SMEM_U32 (B_OFF + 3 * BBUF)           // 24832
#define SMEM_BYTES (SMEM_U32 * 4)             // 99328

__device__ __forceinline__ void issue_stage(
    int tid, uint32_t sm_base, const int* sIdx, int e, int kt, int n0)
{
    const int buf = kt % 3;
#pragma unroll
    for (int i = 0; i < 4; i++) {
        int id = tid + (i << 8);
        int row = id >> 3, ch = id & 7;
        uint32_t wo = (uint32_t)((ch ^ (row & 7)) * 4);
        cp16(sm_base + (X_OFF + buf * XBUF + row * 32 + wo) * 4,
             g_Xh + (size_t)sIdx[row] * D_DIM + kt * 64 + ch * 8);
        cp16(sm_base + (B_OFF + buf * BBUF + row * 32 + wo) * 4,
             g_Wh + ((size_t)e * D_DIM + n0 + row) * D_DIM + kt * 64 + ch * 8);
    }
    asm volatile("cp.async.commit_group;\n" ::: "memory");
}

__global__ __launch_bounds__(256, 2) void moe_mma_kernel(float* __restrict__ out)
{
    const int e = blockIdx.z;
    const int m0 = blockIdx.y * 128;
    const int cnt = g_cnt[e];
    if (m0 >= cnt) return;

    extern __shared__ float smem[];
    int* sIdx = reinterpret_cast<int*>(smem + IDX_OFF);
    float* sW = smem + WV_OFF;
    const uint32_t sm_base = smem_u32(smem);
    const int tid = threadIdx.x;
    const int lane = tid & 31, wid = tid >> 5;
    const int g = lane >> 2, t4 = lane & 3;
    const int n0 = blockIdx.x * 128;
    const int r0 = wid * 16 + g;               // epilogue row base

    // ldmatrix per-lane row/chunk parameters
    const int arow = wid * 16 + (lane & 7) + (lane & 8);   // A row for this lane
    const int akbit = (lane >> 4) & 1;                     // A k8 select
    const int brow_l = (lane & 7) + ((lane & 16) >> 1);    // B row offset in nt-pair
    const int bkbit = (lane >> 3) & 1;                     // B k8 select
    const int l7 = lane & 7;

    if (tid < 128) {
        int idx = m0 + tid;
        if (idx < cnt) {
            sIdx[tid] = g_list[(size_t)e * T_TOK + idx];
            sW[tid]   = g_wval[(size_t)e * T_TOK + idx];
        } else {
            sIdx[tid] = 0;
            sW[tid]   = 0.f;
        }
    }
    __syncthreads();

    float acc[16][4];
#pragma unroll
    for (int nt = 0; nt < 16; nt++)
#pragma unroll
        for (int j = 0; j < 4; j++) acc[nt][j] = 0.f;

    issue_stage(tid, sm_base, sIdx, e, 0, n0);
    issue_stage(tid, sm_base, sIdx, e, 1, n0);

#pragma unroll 1
    for (int kt = 0; kt < 8; ++kt) {
        if (kt + 1 < 8) asm volatile("cp.async.wait_group 1;\n" ::: "memory");
        else            asm volatile("cp.async.wait_group 0;\n" ::: "memory");
        __syncthreads();                       // stage kt ready; buf (kt+2)%3 free
        if (kt + 2 < 8) issue_stage(tid, sm_base, sIdx, e, kt + 2, n0);

        const uint32_t xbase = sm_base + (X_OFF + (kt % 3) * XBUF) * 4;
        const uint32_t bbase = sm_base + (B_OFF + (kt % 3) * BBUF) * 4;

#pragma unroll
        for (int j = 0; j < 2; j++) {          // two k32 halves -> j16 groups x2
#pragma unroll
            for (int jj = 0; jj < 2; jj++) {
                const int jg = j * 2 + jj;     // k16 group 0..3
                uint32_t a0, a1, a2, a3;
                {
                    uint32_t ch = (uint32_t)((jg * 2 + akbit) ^ l7);
                    ldsm_x4(a0, a1, a2, a3, xbase + (arow * 32 + ch * 4) * 4);
                }
                const uint32_t bch = (uint32_t)((jg * 2 + bkbit) ^ l7);
#pragma unroll
                for (int ntp = 0; ntp < 8; ntp++) {
                    uint32_t b0, b1, b2, b3;
                    ldsm_x4(b0, b1, b2, b3,
                            bbase + ((ntp * 16 + brow_l) * 32 + bch * 4) * 4);
                    mma_f16(acc[ntp * 2 + 0], a0, a1, a2, a3, b0, b1);
                    mma_f16(acc[ntp * 2 + 1], a0, a1, a2, a3, b2, b3);
                }
            }
        }
    }

    // ---- epilogue: out[t][n] += w * acc (vector red; pads have w==0) ----
#pragma unroll
    for (int rr = 0; rr < 2; rr++) {
        int row_l = r0 + rr * 8;
        float wv = sW[row_l];
        if (wv > 0.f) {
            float* base = out + (size_t)sIdx[row_l] * D_DIM + n0;
#pragma unroll
            for (int nt = 0; nt < 16; nt++) {
                int cl = nt * 8 + 2 * t4;
                red_add_v2(base + cl, wv * acc[nt][rr * 2 + 0],
                                      wv * acc[nt][rr * 2 + 1]);
            }
        }
    }
}

// ---------------------------------------------------------------------------
extern "C" void kernel_launch(void* const* d_in, const int* in_sizes, int n_in,
                              void* d_out, int out_size)
{
    const float* x    = (const float*)d_in[0];
    const float* Wg   = (const float*)d_in[1];
    const float* bg   = (const float*)d_in[2];
    const float* Wt   = (const float*)d_in[3];
    const float* bt   = (const float*)d_in[4];
    const float* Wexp = (const float*)d_in[5];
    const float* bexp = (const float*)d_in[6];
    float* out        = (float*)d_out;

    const int T = in_sizes[0] / D_DIM;          // 32768

    cudaFuncSetAttribute(moe_mma_kernel,
                         cudaFuncAttributeMaxDynamicSharedMemorySize, SMEM_BYTES);

    wprep_kernel<<<dim3(16, 16, 8), dim3(32, 8)>>>(Wexp);   // also zeroes g_cnt
    gating_kernel<<<T / 8, 256>>>(x, Wg, bg, Wt, bt, bexp, out);
    moe_mma_kernel<<<dim3(4, T / 128, E_DIM), 256, SMEM_BYTES>>>(out);
}